// round 2
// baseline (speedup 1.0000x reference)
#include <cuda_runtime.h>
#include <cuda_bf16.h>

// SNN Leaky (snntorch, reset='subtract'), arithmetic FROZEN from R1 (bit-matches
// the passing run; rel_err 8.8e-4 comes from XLA-vs-CUDA ULP threshold flips):
//   reset = (mem > 1) ? 1 : 0
//   mem   = ((0.95*mem) + x) - reset     [strict __fmul_rn/__fadd_rn/__fsub_rn]
//   spk   = (mem > 1) ? 1 : 0
// Output flat [T, N], N = 3145728, T = 50.
//
// R2 change: 2 float4 per thread (block-split, both stores warp-coalesced 512B),
// compute-both-then-store-both per step -> 2 back-to-back STG.128 per thread per
// step. Doubles outstanding-store MLP (hides DRAM/PTW latency; out spans 629MB
// > 256MB TLB reach) and halves loop overhead per byte.

#define SNN_THREADS 256
#define BETA 0.95f
#define THR  1.0f

__device__ __forceinline__ void snn_step(float& m, float xv, float& s)
{
    const float r = (m > THR) ? THR : 0.0f;
    m = __fsub_rn(__fadd_rn(__fmul_rn(BETA, m), xv), r);
    s = (m > THR) ? 1.0f : 0.0f;
}

template <int NSTEPS>
__global__ __launch_bounds__(SNN_THREADS)
void snn_kernel_v2(const float4* __restrict__ x, float4* __restrict__ out, int n4)
{
    const int i0 = blockIdx.x * (2 * SNN_THREADS) + threadIdx.x;
    const int i1 = i0 + SNN_THREADS;
    const bool has0 = (i0 < n4);
    const bool has1 = (i1 < n4);
    if (!has0) return;

    const float4 xa = x[i0];
    const float4 xb = has1 ? x[i1] : make_float4(0.f, 0.f, 0.f, 0.f);

    float a0 = 0.f, a1 = 0.f, a2 = 0.f, a3 = 0.f;
    float b0 = 0.f, b1 = 0.f, b2 = 0.f, b3 = 0.f;

    float4* oa = out + i0;
    float4* ob = out + i1;

#pragma unroll
    for (int t = 0; t < NSTEPS; ++t) {
        float4 sa, sb;
        snn_step(a0, xa.x, sa.x);
        snn_step(a1, xa.y, sa.y);
        snn_step(a2, xa.z, sa.z);
        snn_step(a3, xa.w, sa.w);
        snn_step(b0, xb.x, sb.x);
        snn_step(b1, xb.y, sb.y);
        snn_step(b2, xb.z, sb.z);
        snn_step(b3, xb.w, sb.w);

        const size_t off = (size_t)t * n4;
        __stcs(oa + off, sa);                 // two back-to-back streaming
        if (has1) __stcs(ob + off, sb);       // STG.128 -> deeper store MLP
    }
}

// Generic runtime step count, same structure.
__global__ __launch_bounds__(SNN_THREADS)
void snn_kernel_v2_gen(const float4* __restrict__ x, float4* __restrict__ out,
                       int n4, int nsteps)
{
    const int i0 = blockIdx.x * (2 * SNN_THREADS) + threadIdx.x;
    const int i1 = i0 + SNN_THREADS;
    const bool has0 = (i0 < n4);
    const bool has1 = (i1 < n4);
    if (!has0) return;

    const float4 xa = x[i0];
    const float4 xb = has1 ? x[i1] : make_float4(0.f, 0.f, 0.f, 0.f);

    float a0 = 0.f, a1 = 0.f, a2 = 0.f, a3 = 0.f;
    float b0 = 0.f, b1 = 0.f, b2 = 0.f, b3 = 0.f;

    float4* oa = out + i0;
    float4* ob = out + i1;

    for (int t = 0; t < nsteps; ++t) {
        float4 sa, sb;
        snn_step(a0, xa.x, sa.x);
        snn_step(a1, xa.y, sa.y);
        snn_step(a2, xa.z, sa.z);
        snn_step(a3, xa.w, sa.w);
        snn_step(b0, xb.x, sb.x);
        snn_step(b1, xb.y, sb.y);
        snn_step(b2, xb.z, sb.z);
        snn_step(b3, xb.w, sb.w);

        const size_t off = (size_t)t * n4;
        __stcs(oa + off, sa);
        if (has1) __stcs(ob + off, sb);
    }
}

// Scalar tail for n % 4 != 0 (not hit for this shape).
__global__ __launch_bounds__(SNN_THREADS)
void snn_kernel_tail(const float* __restrict__ x, float* __restrict__ out,
                     int start, int n, int nsteps)
{
    int i = start + blockIdx.x * SNN_THREADS + threadIdx.x;
    if (i >= n) return;

    const float xv = x[i];
    float m = 0.0f;
    for (int t = 0; t < nsteps; ++t) {
        const float r = (m > THR) ? THR : 0.0f;
        m = __fsub_rn(__fadd_rn(__fmul_rn(BETA, m), xv), r);
        out[(size_t)t * n + i] = (m > THR) ? 1.0f : 0.0f;
    }
}

extern "C" void kernel_launch(void* const* d_in, const int* in_sizes, int n_in,
                              void* d_out, int out_size)
{
    const float* x = (const float*)d_in[0];
    float* out = (float*)d_out;

    const int n = in_sizes[0];          // 3,145,728
    const int nsteps = out_size / n;    // 50

    const int n4 = n / 4;               // 786,432 float4s
    const int tail = n - n4 * 4;

    if (n4 > 0) {
        const int per_block = 2 * SNN_THREADS;
        const int grid = (n4 + per_block - 1) / per_block;   // 1536 for this shape
        if (nsteps == 50) {
            snn_kernel_v2<50><<<grid, SNN_THREADS>>>(
                (const float4*)x, (float4*)out, n4);
        } else {
            snn_kernel_v2_gen<<<grid, SNN_THREADS>>>(
                (const float4*)x, (float4*)out, n4, nsteps);
        }
    }
    if (tail > 0) {
        snn_kernel_tail<<<1, SNN_THREADS>>>(x, out, n4 * 4, n, nsteps);
    }
}